// round 2
// baseline (speedup 1.0000x reference)
#include <cuda_runtime.h>
#include <math.h>
#include <stdint.h>

// ---------------------------------------------------------------------------
// HashEncoderHyFluid: 4D multi-resolution hash grid encoding.
//   N queries (xyzt in [0,1)^4), 16 levels, F=2 features, 16 hypercube corners.
//   out[n, s*2 + f] = sum_{c=0..15} w_c * table[offset_s + 2*idx_c + f]
// Dense levels (raw <= size): linear index, no mod needed (idx < size).
// Hashed levels: size is always 2^19 -> mask. (raw > 2^19 forces p = 2^19.)
// ---------------------------------------------------------------------------

struct Level {
    float    rf0, rf1, rf2, rf3;   // res as float32 (matches res.astype(np.float32))
    unsigned s1, s2, s3;           // dense strides: r0+1, (r0+1)(r1+1), (r0+1)(r1+1)(r2+1)
    unsigned mask;                 // size-1 (hashed, pow2)
    unsigned size;                 // params at this level
    int      offset;               // float offset into hash_table
    int      mode;                 // 0 = dense, 1 = hash + mask, 2 = hash + mod
};
struct KConfig { Level lv[16]; };

#define HPRIME1 2654435761u
#define HPRIME2 805459861u
#define HPRIME3 3674653429u

__global__ __launch_bounds__(256)
void hashenc_kernel(const float4* __restrict__ xyzt,
                    const float*  __restrict__ tab,
                    float*        __restrict__ out,
                    KConfig cfg, int n)
{
    int q = blockIdx.x * 256 + threadIdx.x;
    if (q >= n) return;

    float4 X = xyzt[q];
    float2* outq = reinterpret_cast<float2*>(out + (size_t)q * 32);

    #pragma unroll 1
    for (int s = 0; s < 16; ++s) {
        Level L = cfg.lv[s];

        // grid-space position, cell, fractional part (all f32, same ops as JAX)
        float px = X.x * L.rf0, py = X.y * L.rf1, pz = X.z * L.rf2, pt = X.w * L.rf3;
        float gx = floorf(px),  gy = floorf(py),  gz = floorf(pz),  gt = floorf(pt);
        float fx = px - gx,     fy = py - gy,     fz = pz - gz,     ft = pt - gt;
        unsigned cx = (unsigned)(int)gx, cy = (unsigned)(int)gy;
        unsigned cz = (unsigned)(int)gz, ct = (unsigned)(int)gt;

        // factorized trilinear weights: w(i) = wxy[i&3] * wzt[i>>2]
        float wx0 = 1.f - fx, wy0 = 1.f - fy, wz0 = 1.f - fz, wt0 = 1.f - ft;
        float wxy[4], wzt[4];
        wxy[0] = wx0 * wy0;  wxy[1] = fx * wy0;  wxy[2] = wx0 * fy;  wxy[3] = fx * fy;
        wzt[0] = wz0 * wt0;  wzt[1] = fz * wt0;  wzt[2] = wz0 * ft;  wzt[3] = fz * ft;

        const float2* t2 = reinterpret_cast<const float2*>(tab) + (L.offset >> 1);
        float a0 = 0.f, a1 = 0.f;

        if (L.mode == 0) {
            // dense: idx = cx + cy*s1 + cz*s2 + ct*s3 (+corner bits); idx < size, no mod
            unsigned bxy = cx + cy * L.s1;
            unsigned ixy[4] = { bxy, bxy + 1u, bxy + L.s1, bxy + L.s1 + 1u };
            unsigned bzt = cz * L.s2 + ct * L.s3;
            unsigned izt[4] = { bzt, bzt + L.s2, bzt + L.s3, bzt + L.s2 + L.s3 };
            #pragma unroll
            for (int i = 0; i < 16; ++i) {
                unsigned idx = ixy[i & 3] + izt[i >> 2];
                float w = wxy[i & 3] * wzt[i >> 2];
                float2 f = __ldg(t2 + idx);
                a0 += w * f.x;
                a1 += w * f.y;
            }
        } else {
            // hashed: h = cx*1 ^ cy*P1 ^ cz*P2 ^ ct*P3, then mask (size = 2^19)
            unsigned hy = cy * HPRIME1, hz = cz * HPRIME2, ht = ct * HPRIME3;
            unsigned ixy[4] = { cx ^ hy, (cx + 1u) ^ hy,
                                cx ^ (hy + HPRIME1), (cx + 1u) ^ (hy + HPRIME1) };
            unsigned izt[4] = { hz ^ ht, (hz + HPRIME2) ^ ht,
                                hz ^ (ht + HPRIME3), (hz + HPRIME2) ^ (ht + HPRIME3) };
            if (L.mode == 1) {
                unsigned msk = L.mask;
                #pragma unroll
                for (int i = 0; i < 16; ++i) {
                    unsigned idx = (ixy[i & 3] ^ izt[i >> 2]) & msk;
                    float w = wxy[i & 3] * wzt[i >> 2];
                    float2 f = __ldg(t2 + idx);
                    a0 += w * f.x;
                    a1 += w * f.y;
                }
            } else {
                // safety fallback (never taken with current constants)
                unsigned sz = L.size;
                #pragma unroll
                for (int i = 0; i < 16; ++i) {
                    unsigned idx = (ixy[i & 3] ^ izt[i >> 2]) % sz;
                    float w = wxy[i & 3] * wzt[i >> 2];
                    float2 f = __ldg(t2 + idx);
                    a0 += w * f.x;
                    a1 += w * f.y;
                }
            }
        }
        *outq = make_float2(a0, a1);
        ++outq;
    }
}

// ---------------------------------------------------------------------------
// Host-side config: mirrors reference build_config() op-for-op in float64.
// On the aarch64 GPU host, NumPy float64 exp/log/pow route to the same glibc
// libm this host code links against -> bit-exact resolutions (including the
// near-integer ceil points at 16*b_t^5 ~ 32, 16*b^15 ~ 256).
// ---------------------------------------------------------------------------
static KConfig build_cfg_host()
{
    const double minr[4] = {16.0, 16.0, 16.0, 16.0};
    const double maxr[4] = {256.0, 256.0, 256.0, 128.0};
    const long long MAXP = 524288; // 2^19

    double b[4];
    for (int d = 0; d < 4; ++d)
        b[d] = exp((log(maxr[d]) - log(minr[d])) / 15.0);

    KConfig cfg;
    long long total = 0;
    for (int s = 0; s < 16; ++s) {
        long long res[4];
        for (int d = 0; d < 4; ++d)
            res[d] = (long long)ceil(minr[d] * pow(b[d], (double)s));
        long long raw = (res[0] + 1) * (res[1] + 1) * (res[2] + 1) * (res[3] + 1);
        long long p = (raw % 8 == 0) ? raw : ((raw + 7) / 8) * 8;
        if (p > MAXP) p = MAXP;
        int dense = (raw <= p) ? 1 : 0;

        Level& L = cfg.lv[s];
        L.rf0 = (float)res[0]; L.rf1 = (float)res[1];
        L.rf2 = (float)res[2]; L.rf3 = (float)res[3];
        L.s1 = (unsigned)(res[0] + 1);
        L.s2 = (unsigned)((res[0] + 1) * (res[1] + 1));
        L.s3 = (unsigned)((res[0] + 1) * (res[1] + 1) * (res[2] + 1));
        L.size = (unsigned)p;
        L.mask = (unsigned)(p - 1);
        L.offset = (int)total;
        if (dense)                      L.mode = 0;
        else if ((p & (p - 1)) == 0)    L.mode = 1;   // pow2 -> mask
        else                            L.mode = 2;   // generic mod fallback
        total += p * 2;  // F = 2
    }
    return cfg;
}

extern "C" void kernel_launch(void* const* d_in, const int* in_sizes, int n_in,
                              void* d_out, int out_size)
{
    static KConfig cfg = build_cfg_host();   // computed once, host math only

    const float4* xyzt = (const float4*)d_in[0];
    const float*  tab  = (const float*)d_in[1];
    float*        out  = (float*)d_out;

    int n = in_sizes[0] / 4;
    int blocks = (n + 255) / 256;
    hashenc_kernel<<<blocks, 256>>>(xyzt, tab, out, cfg, n);
}

// round 3
// speedup vs baseline: 1.0758x; 1.0758x over previous
#include <cuda_runtime.h>
#include <math.h>
#include <stdint.h>

// ---------------------------------------------------------------------------
// HashEncoderHyFluid: 4D multi-resolution hash grid encoding.
// R2: x-pair corner merging. PRIMES[0]==1 => for even cx the two x-corners of
// every pair hash to indices differing only in bit0 -> one aligned LDG.128
// fetches both float2 entries (1 wavefront + 1 L2 sector instead of 2 each).
// Dense levels: idx1 = idx0+1, pairable iff idx0 even (per-pair predicate).
// ---------------------------------------------------------------------------

struct Level {
    float    rf0, rf1, rf2, rf3;   // res as float32
    unsigned s1, s2, s3;           // dense strides
    unsigned mask;                 // size-1 (hashed pow2)
    unsigned size;                 // params at this level
    int      offset;               // float offset into hash_table
    int      mode;                 // 0 = dense, 1 = hash + mask, 2 = hash + mod
};
struct KConfig { Level lv[16]; };

#define HPRIME1 2654435761u
#define HPRIME2 805459861u
#define HPRIME3 3674653429u

// accumulate an x-pair from one aligned float4 covering entries {m, m+1}
__device__ __forceinline__ void acc_pair128(const float2* __restrict__ t2,
                                            unsigned i0, float w0, float w1,
                                            float& a0, float& a1)
{
    unsigned m = i0 & ~1u;
    float4 f = __ldg(reinterpret_cast<const float4*>(t2 + m));
    bool odd = (i0 & 1u);
    float c0x = odd ? f.z : f.x, c0y = odd ? f.w : f.y;   // corner x-bit 0
    float c1x = odd ? f.x : f.z, c1y = odd ? f.y : f.w;   // corner x-bit 1
    a0 += w0 * c0x + w1 * c1x;
    a1 += w0 * c0y + w1 * c1y;
}

__global__ __launch_bounds__(256)
void hashenc_kernel(const float4* __restrict__ xyzt,
                    const float*  __restrict__ tab,
                    float*        __restrict__ out,
                    KConfig cfg, int n)
{
    int q = blockIdx.x * 256 + threadIdx.x;
    if (q >= n) return;

    float4 X = xyzt[q];
    float2* outq = reinterpret_cast<float2*>(out + (size_t)q * 32);

    #pragma unroll 1
    for (int s = 0; s < 16; ++s) {
        Level L = cfg.lv[s];

        float px = X.x * L.rf0, py = X.y * L.rf1, pz = X.z * L.rf2, pt = X.w * L.rf3;
        float gx = floorf(px),  gy = floorf(py),  gz = floorf(pz),  gt = floorf(pt);
        float fx = px - gx,     fy = py - gy,     fz = pz - gz,     ft = pt - gt;
        unsigned cx = (unsigned)(int)gx, cy = (unsigned)(int)gy;
        unsigned cz = (unsigned)(int)gz, ct = (unsigned)(int)gt;

        float wx0 = 1.f - fx, wy0 = 1.f - fy, wz0 = 1.f - fz, wt0 = 1.f - ft;
        float wxy[4], wzt[4];
        wxy[0] = wx0 * wy0;  wxy[1] = fx * wy0;  wxy[2] = wx0 * fy;  wxy[3] = fx * fy;
        wzt[0] = wz0 * wt0;  wzt[1] = fz * wt0;  wzt[2] = wz0 * ft;  wzt[3] = fz * ft;

        const float2* t2 = reinterpret_cast<const float2*>(tab) + (L.offset >> 1);
        float a0 = 0.f, a1 = 0.f;

        if (L.mode == 0) {
            // dense: idx = cx + cy*s1 + cz*s2 + ct*s3 (+bits); idx < size, no mod.
            unsigned bxy = cx + cy * L.s1;
            unsigned ixy0[2] = { bxy, bxy + L.s1 };          // x-bit 0, per y-bit
            unsigned bzt = cz * L.s2 + ct * L.s3;
            unsigned izt[4] = { bzt, bzt + L.s2, bzt + L.s3, bzt + L.s2 + L.s3 };
            #pragma unroll
            for (int j = 0; j < 4; ++j) {
                #pragma unroll
                for (int b = 0; b < 2; ++b) {
                    unsigned i0 = ixy0[b] + izt[j];          // x-bit 0 corner
                    float w0 = wxy[2 * b]     * wzt[j];
                    float w1 = wxy[2 * b + 1] * wzt[j];
                    if ((i0 & 1u) == 0u) {                   // i1 = i0+1 = i0^1
                        acc_pair128(t2, i0, w0, w1, a0, a1);
                    } else {
                        float2 f0 = __ldg(t2 + i0);
                        float2 f1 = __ldg(t2 + i0 + 1u);
                        a0 += w0 * f0.x + w1 * f1.x;
                        a1 += w0 * f0.y + w1 * f1.y;
                    }
                }
            }
        } else {
            // hashed: h = cx ^ cy*P1 ^ cz*P2 ^ ct*P3 (PRIMES[0]==1), size = 2^19
            unsigned hy = cy * HPRIME1, hz = cz * HPRIME2, ht = ct * HPRIME3;
            unsigned msk = L.mask;
            unsigned rxy0[2] = { hy, hy + HPRIME1 };         // y-part per y-bit
            unsigned izt[4] = { hz ^ ht, (hz + HPRIME2) ^ ht,
                                hz ^ (ht + HPRIME3), (hz + HPRIME2) ^ (ht + HPRIME3) };
            if (L.mode == 1) {
                if ((cx & 1u) == 0u) {
                    // cx even: (cx+1)^R = (cx^R)^1 -> every x-pair is one float4
                    #pragma unroll
                    for (int j = 0; j < 4; ++j) {
                        #pragma unroll
                        for (int b = 0; b < 2; ++b) {
                            unsigned i0 = (cx ^ rxy0[b] ^ izt[j]) & msk;
                            acc_pair128(t2, i0,
                                        wxy[2 * b] * wzt[j], wxy[2 * b + 1] * wzt[j],
                                        a0, a1);
                        }
                    }
                } else {
                    unsigned cx1 = cx + 1u;
                    #pragma unroll
                    for (int j = 0; j < 4; ++j) {
                        #pragma unroll
                        for (int b = 0; b < 2; ++b) {
                            unsigned r = rxy0[b] ^ izt[j];
                            unsigned i0 = (cx  ^ r) & msk;
                            unsigned i1 = (cx1 ^ r) & msk;
                            float w0 = wxy[2 * b]     * wzt[j];
                            float w1 = wxy[2 * b + 1] * wzt[j];
                            float2 f0 = __ldg(t2 + i0);
                            float2 f1 = __ldg(t2 + i1);
                            a0 += w0 * f0.x + w1 * f1.x;
                            a1 += w0 * f0.y + w1 * f1.y;
                        }
                    }
                }
            } else {
                // generic mod fallback (never taken with current constants)
                unsigned sz = L.size, cx1 = cx + 1u;
                #pragma unroll
                for (int j = 0; j < 4; ++j) {
                    #pragma unroll
                    for (int b = 0; b < 2; ++b) {
                        unsigned r = rxy0[b] ^ izt[j];
                        unsigned i0 = (cx  ^ r) % sz;
                        unsigned i1 = (cx1 ^ r) % sz;
                        float w0 = wxy[2 * b]     * wzt[j];
                        float w1 = wxy[2 * b + 1] * wzt[j];
                        float2 f0 = __ldg(t2 + i0);
                        float2 f1 = __ldg(t2 + i1);
                        a0 += w0 * f0.x + w1 * f1.x;
                        a1 += w0 * f0.y + w1 * f1.y;
                    }
                }
            }
        }
        *outq = make_float2(a0, a1);
        ++outq;
    }
}

// ---------------------------------------------------------------------------
// Host-side config: mirrors reference build_config() op-for-op in float64.
// ---------------------------------------------------------------------------
static KConfig build_cfg_host()
{
    const double minr[4] = {16.0, 16.0, 16.0, 16.0};
    const double maxr[4] = {256.0, 256.0, 256.0, 128.0};
    const long long MAXP = 524288; // 2^19

    double b[4];
    for (int d = 0; d < 4; ++d)
        b[d] = exp((log(maxr[d]) - log(minr[d])) / 15.0);

    KConfig cfg;
    long long total = 0;
    for (int s = 0; s < 16; ++s) {
        long long res[4];
        for (int d = 0; d < 4; ++d)
            res[d] = (long long)ceil(minr[d] * pow(b[d], (double)s));
        long long raw = (res[0] + 1) * (res[1] + 1) * (res[2] + 1) * (res[3] + 1);
        long long p = (raw % 8 == 0) ? raw : ((raw + 7) / 8) * 8;
        if (p > MAXP) p = MAXP;
        int dense = (raw <= p) ? 1 : 0;

        Level& L = cfg.lv[s];
        L.rf0 = (float)res[0]; L.rf1 = (float)res[1];
        L.rf2 = (float)res[2]; L.rf3 = (float)res[3];
        L.s1 = (unsigned)(res[0] + 1);
        L.s2 = (unsigned)((res[0] + 1) * (res[1] + 1));
        L.s3 = (unsigned)((res[0] + 1) * (res[1] + 1) * (res[2] + 1));
        L.size = (unsigned)p;
        L.mask = (unsigned)(p - 1);
        L.offset = (int)total;
        if (dense)                      L.mode = 0;
        else if ((p & (p - 1)) == 0)    L.mode = 1;
        else                            L.mode = 2;
        total += p * 2;  // F = 2
    }
    return cfg;
}

extern "C" void kernel_launch(void* const* d_in, const int* in_sizes, int n_in,
                              void* d_out, int out_size)
{
    static KConfig cfg = build_cfg_host();

    const float4* xyzt = (const float4*)d_in[0];
    const float*  tab  = (const float*)d_in[1];
    float*        out  = (float*)d_out;

    int n = in_sizes[0] / 4;
    int blocks = (n + 255) / 256;
    hashenc_kernel<<<blocks, 256>>>(xyzt, tab, out, cfg, n);
}